// round 1
// baseline (speedup 1.0000x reference)
#include <cuda_runtime.h>
#include <math.h>

// Problem constants
#define Bn 4
#define Sn 1024
#define Dn 1024
#define Hn 16
#define HDn 64
#define NEGV -10000000.0f

// Scratch for Q, K, V in [B, H, S, HD] layout (no cudaMalloc allowed)
__device__ float QKVd[3][Bn * Hn * Sn * HDn];

// ---------------------------------------------------------------------------
// SGEMM: Out[b,h,s,hd] = (X @ W + bias) with heads remap
// X: [4096, 1024] row-major, W: [1024, 1024] row-major
// Tiles: BM=BN=128, BK=8, per-thread 8x8, 256 threads
// ---------------------------------------------------------------------------
#define BM 128
#define BN 128
#define BK 8
#define TM 8
#define TN 8

__global__ __launch_bounds__(256)
void gemm_qkv_kernel(const float* __restrict__ X, const float* __restrict__ W,
                     const float* __restrict__ bias, int which) {
    __shared__ float As[BK][BM + 4];
    __shared__ float Bs[BK][BN + 4];

    const int tid = threadIdx.x;
    const int tx = tid & 15;      // 0..15
    const int ty = tid >> 4;      // 0..15
    const int m0 = blockIdx.y * BM;
    const int n0 = blockIdx.x * BN;
    const int K = 1024, N = 1024;

    // Load mapping
    const int aRow = tid >> 1;          // 0..127
    const int aCol = (tid & 1) * 4;     // 0 or 4
    const int bRow = tid >> 5;          // 0..7
    const int bCol = (tid & 31) * 4;    // 0..124

    float acc[TM][TN];
#pragma unroll
    for (int i = 0; i < TM; i++)
#pragma unroll
        for (int j = 0; j < TN; j++) acc[i][j] = 0.0f;

    for (int k0 = 0; k0 < K; k0 += BK) {
        float4 a4 = *(const float4*)&X[(size_t)(m0 + aRow) * K + k0 + aCol];
        As[aCol + 0][aRow] = a4.x;
        As[aCol + 1][aRow] = a4.y;
        As[aCol + 2][aRow] = a4.z;
        As[aCol + 3][aRow] = a4.w;
        float4 b4 = *(const float4*)&W[(size_t)(k0 + bRow) * N + n0 + bCol];
        *(float4*)&Bs[bRow][bCol] = b4;
        __syncthreads();

#pragma unroll
        for (int k = 0; k < BK; k++) {
            float ra[TM], rb[TN];
#pragma unroll
            for (int i = 0; i < TM; i++) ra[i] = As[k][ty * TM + i];
#pragma unroll
            for (int j = 0; j < TN; j++) rb[j] = Bs[k][tx * TN + j];
#pragma unroll
            for (int i = 0; i < TM; i++)
#pragma unroll
                for (int j = 0; j < TN; j++) acc[i][j] += ra[i] * rb[j];
        }
        __syncthreads();
    }

    // Epilogue: add bias, remap [m, n] -> [b, h, s, hd]
    float* Out = QKVd[which];
#pragma unroll
    for (int i = 0; i < TM; i++) {
        const int m = m0 + ty * TM + i;
        const int b = m >> 10;
        const int s = m & 1023;
#pragma unroll
        for (int j0 = 0; j0 < TN; j0 += 4) {
            const int n = n0 + tx * TN + j0;
            const int hh = n >> 6;
            const int hd = n & 63;
            float4 w;
            w.x = acc[i][j0 + 0] + bias[n + 0];
            w.y = acc[i][j0 + 1] + bias[n + 1];
            w.z = acc[i][j0 + 2] + bias[n + 2];
            w.w = acc[i][j0 + 3] + bias[n + 3];
            const size_t idx = (((size_t)(b * Hn + hh) * Sn + s) * HDn + hd);
            *(float4*)&Out[idx] = w;
        }
    }
}

// ---------------------------------------------------------------------------
// Flash-attention with adjacency mask.
// Block: (bh = b*H + h, q-tile of 64). 256 threads, 4x4 microtiles.
// Online softmax across 16 k-tiles of 64.
// ---------------------------------------------------------------------------
#define QT 64     // q rows per block
#define KT 64     // k cols per tile
#define PAD 68    // padded row stride (avoid bank conflicts)

__global__ __launch_bounds__(256)
void attn_kernel(const float* __restrict__ adj, float* __restrict__ out) {
    extern __shared__ float sm[];
    float* Qs = sm;                    // 64 x 68
    float* Ks = Qs + QT * PAD;         // 64 x 68
    float* Vs = Ks + QT * PAD;         // 64 x 68
    float* Ss = Vs + QT * PAD;         // 64 x 68
    float* mrow = Ss + QT * PAD;       // 64
    float* lrow = mrow + QT;           // 64
    float* arow = lrow + QT;           // 64

    const int bh = blockIdx.x;         // 0..63
    const int q0 = blockIdx.y * QT;
    const int b = bh >> 4;
    const int hh = bh & 15;
    const int tid = threadIdx.x;
    const int tx = tid & 15;           // 0..15 -> hd / k-col groups
    const int ty = tid >> 4;           // 0..15 -> q-row groups

    const float* Qg = QKVd[0] + (size_t)bh * Sn * HDn;
    const float* Kg = QKVd[1] + (size_t)bh * Sn * HDn;
    const float* Vg = QKVd[2] + (size_t)bh * Sn * HDn;
    const float* adjg = adj + (size_t)b * Sn * Sn + (size_t)q0 * Sn;

    // Load Q tile (64 x 64)
    for (int i = tid; i < QT * 16; i += 256) {
        const int r = i >> 4;
        const int c = (i & 15) * 4;
        float4 v4 = *(const float4*)&Qg[(size_t)(q0 + r) * HDn + c];
        Qs[r * PAD + c + 0] = v4.x;
        Qs[r * PAD + c + 1] = v4.y;
        Qs[r * PAD + c + 2] = v4.z;
        Qs[r * PAD + c + 3] = v4.w;
    }
    if (tid < QT) { mrow[tid] = -INFINITY; lrow[tid] = 0.0f; }

    float o[4][4];
#pragma unroll
    for (int i = 0; i < 4; i++)
#pragma unroll
        for (int j = 0; j < 4; j++) o[i][j] = 0.0f;

    const float scale = 0.125f;  // 1/sqrt(64)
    __syncthreads();

    for (int k0 = 0; k0 < Sn; k0 += KT) {
        // Load K and V tiles
        for (int i = tid; i < KT * 16; i += 256) {
            const int r = i >> 4;
            const int c = (i & 15) * 4;
            float4 kv = *(const float4*)&Kg[(size_t)(k0 + r) * HDn + c];
            Ks[r * PAD + c + 0] = kv.x;
            Ks[r * PAD + c + 1] = kv.y;
            Ks[r * PAD + c + 2] = kv.z;
            Ks[r * PAD + c + 3] = kv.w;
            float4 vv = *(const float4*)&Vg[(size_t)(k0 + r) * HDn + c];
            Vs[r * PAD + c + 0] = vv.x;
            Vs[r * PAD + c + 1] = vv.y;
            Vs[r * PAD + c + 2] = vv.z;
            Vs[r * PAD + c + 3] = vv.w;
        }
        __syncthreads();

        // Scores microtile: q rows ty*4.., k cols tx*4..
        float s4[4][4];
#pragma unroll
        for (int i = 0; i < 4; i++)
#pragma unroll
            for (int j = 0; j < 4; j++) s4[i][j] = 0.0f;

#pragma unroll
        for (int d = 0; d < HDn; d++) {
            float qa[4], kb[4];
#pragma unroll
            for (int i = 0; i < 4; i++) qa[i] = Qs[(ty * 4 + i) * PAD + d];
#pragma unroll
            for (int j = 0; j < 4; j++) kb[j] = Ks[(tx * 4 + j) * PAD + d];
#pragma unroll
            for (int i = 0; i < 4; i++)
#pragma unroll
                for (int j = 0; j < 4; j++) s4[i][j] += qa[i] * kb[j];
        }

        // Apply scale + adjacency mask, write scores to smem
#pragma unroll
        for (int i = 0; i < 4; i++) {
            const int qr = ty * 4 + i;
            float4 a4 = *(const float4*)&adjg[(size_t)qr * Sn + k0 + tx * 4];
            float av[4] = {a4.x, a4.y, a4.z, a4.w};
#pragma unroll
            for (int j = 0; j < 4; j++) {
                float v = s4[i][j] * scale + (av[j] < 0.5f ? NEGV : 0.0f);
                Ss[qr * PAD + tx * 4 + j] = v;
            }
        }
        __syncthreads();

        // Online softmax per row. 4 threads per row (consecutive lanes).
        {
            const int r = tid >> 2;
            const int part = tid & 3;
            float mx = -INFINITY;
            const int c0 = part * 16;
#pragma unroll
            for (int c = 0; c < 16; c++) mx = fmaxf(mx, Ss[r * PAD + c0 + c]);
            mx = fmaxf(mx, __shfl_xor_sync(0xffffffffu, mx, 1));
            mx = fmaxf(mx, __shfl_xor_sync(0xffffffffu, mx, 2));
            const float mold = mrow[r];
            const float mnew = fmaxf(mold, mx);
            float sum = 0.0f;
#pragma unroll
            for (int c = 0; c < 16; c++) {
                float p = __expf(Ss[r * PAD + c0 + c] - mnew);
                Ss[r * PAD + c0 + c] = p;
                sum += p;
            }
            sum += __shfl_xor_sync(0xffffffffu, sum, 1);
            sum += __shfl_xor_sync(0xffffffffu, sum, 2);
            if (part == 0) {
                const float alpha = __expf(mold - mnew);  // 0 on first tile
                mrow[r] = mnew;
                lrow[r] = lrow[r] * alpha + sum;
                arow[r] = alpha;
            }
        }
        __syncthreads();

        // Rescale accumulators and accumulate P @ V
        float al[4];
#pragma unroll
        for (int i = 0; i < 4; i++) al[i] = arow[ty * 4 + i];
#pragma unroll
        for (int i = 0; i < 4; i++)
#pragma unroll
            for (int j = 0; j < 4; j++) o[i][j] *= al[i];

#pragma unroll
        for (int k = 0; k < KT; k++) {
            float p[4], vv[4];
#pragma unroll
            for (int i = 0; i < 4; i++) p[i] = Ss[(ty * 4 + i) * PAD + k];
#pragma unroll
            for (int j = 0; j < 4; j++) vv[j] = Vs[k * PAD + tx * 4 + j];
#pragma unroll
            for (int i = 0; i < 4; i++)
#pragma unroll
                for (int j = 0; j < 4; j++) o[i][j] += p[i] * vv[j];
        }
        __syncthreads();  // before next tile overwrites Ks/Vs/Ss
    }

    // Epilogue: normalize, relu, write h[b, s, h*64 + hd]
#pragma unroll
    for (int i = 0; i < 4; i++) {
        const int r = ty * 4 + i;
        const float inv = 1.0f / lrow[r];
        const int s = q0 + r;
        float4 w;
        w.x = fmaxf(o[i][0] * inv, 0.0f);
        w.y = fmaxf(o[i][1] * inv, 0.0f);
        w.z = fmaxf(o[i][2] * inv, 0.0f);
        w.w = fmaxf(o[i][3] * inv, 0.0f);
        const size_t idx = ((size_t)(b * Sn + s)) * Dn + hh * HDn + tx * 4;
        *(float4*)&out[idx] = w;
    }
}

// ---------------------------------------------------------------------------
// adj passthrough copy (second half of output tuple)
// ---------------------------------------------------------------------------
__global__ __launch_bounds__(256)
void copy_adj_kernel(const float4* __restrict__ src, float4* __restrict__ dst, int n4) {
    int i = blockIdx.x * blockDim.x + threadIdx.x;
    if (i < n4) dst[i] = src[i];
}

// ---------------------------------------------------------------------------
extern "C" void kernel_launch(void* const* d_in, const int* in_sizes, int n_in,
                              void* d_out, int out_size) {
    const float* x   = (const float*)d_in[0];
    const float* adj = (const float*)d_in[1];
    const float* Wq  = (const float*)d_in[2];
    const float* bq  = (const float*)d_in[3];
    const float* Wk  = (const float*)d_in[4];
    const float* bk  = (const float*)d_in[5];
    const float* Wv  = (const float*)d_in[6];
    const float* bv  = (const float*)d_in[7];
    float* out = (float*)d_out;

    // QKV projections
    dim3 gg(Dn / BN, (Bn * Sn) / BM);  // (8, 32)
    gemm_qkv_kernel<<<gg, 256>>>(x, Wq, bq, 0);
    gemm_qkv_kernel<<<gg, 256>>>(x, Wk, bk, 1);
    gemm_qkv_kernel<<<gg, 256>>>(x, Wv, bv, 2);

    // Attention
    const int smem_bytes = (4 * QT * PAD + 3 * QT) * (int)sizeof(float);  // ~70.4 KB
    cudaFuncSetAttribute(attn_kernel, cudaFuncAttributeMaxDynamicSharedMemorySize,
                         smem_bytes);
    attn_kernel<<<dim3(Bn * Hn, Sn / QT), 256, smem_bytes>>>(adj, out);

    // adj copy into second half of output
    const int n_h = Bn * Sn * Dn;        // 4194304
    const int n4 = (Bn * Sn * Sn) / 4;   // 1048576
    copy_adj_kernel<<<(n4 + 255) / 256, 256>>>((const float4*)adj,
                                               (float4*)(out + n_h), n4);
}